// round 3
// baseline (speedup 1.0000x reference)
#include <cuda_runtime.h>
#include <cstdint>

// x:      (2, 64, 32, 32, 32) fp32
// weight: (64, 32, 3, 3, 3)   fp32  (C_in, C_out, kD,kH,kW)
// bias:   (32,)               fp32
// out:    (2, 32, 66, 66, 66) fp32
//
// Only outputs with all-odd coords <= 63 carry conv data:
//   core[z] = sum_{ci,k} W[ci,co,2-kd,2-kh,2-kw] * x[ci, z-1+k]
// Everything else is bias-only.

#define N_BATCH 2
#define CI 64
#define CO 32
#define IN_S 32
#define OUT_S 66
#define CIC 8          // ci per smem chunk
#define NCHUNK (CI / CIC)
#define CH_STRIDE 287496   // 66^3
#define OUT_TOTAL 18399744 // 2*32*66^3
#define OUT_F4 (OUT_TOTAL / 4)
#define CH_F4 (CH_STRIDE / 4)

// ---------------------------------------------------------------------------
// Kernel 1: bias fill (vectorized float4). CH_STRIDE % 4 == 0 so each float4
// lies within one (n,co) channel.
// ---------------------------------------------------------------------------
__global__ void bias_fill_kernel(const float* __restrict__ bias,
                                 float* __restrict__ out) {
    int idx4 = blockIdx.x * blockDim.x + threadIdx.x;
    if (idx4 >= OUT_F4) return;
    int ch = idx4 / CH_F4;
    float b = __ldg(&bias[ch & 31]);
    reinterpret_cast<float4*>(out)[idx4] = make_float4(b, b, b, b);
}

// ---------------------------------------------------------------------------
// Kernel 2: dense 32^3 core conv.
// Block = 512 threads = one (8,8,8) z-tile, thread (ld,lh,lw) owns ONE point
// for all 32 output channels (16 packed f32x2 accumulators).
// Grid = (4,4,8) = 128 blocks -> one CTA per SM, single wave, 16 warps/SM.
// Per tap per thread: 1 LDS.32 (x) + 8 LDS.128 (broadcast w) + 16 fma.f32x2.
// ---------------------------------------------------------------------------
__global__ void __launch_bounds__(512, 1)
conv_core_kernel(const float* __restrict__ x,
                 const float* __restrict__ w,
                 const float* __restrict__ bias,
                 float* __restrict__ out) {
    // x halo tile: [ci][10][10][10], zero-padded outside [0,32)
    __shared__ __align__(16) float xs[CIC][10][10][10];   // 32 KB
    // flipped weights: ws[ci][k][co], value = W[ci,co, 26-k]
    __shared__ __align__(16) float ws[CIC][27][CO];       // 27.6 KB

    const int tid = threadIdx.x;
    const int lw = tid & 7;
    const int lh = (tid >> 3) & 7;
    const int ld = tid >> 6;          // 0..7

    const int tw = blockIdx.x;        // 0..3
    const int th = blockIdx.y;        // 0..3
    const int nz = blockIdx.z;        // 0..7
    const int n  = nz >> 2;
    const int td = nz & 3;

    const int zd0 = td * 8;
    const int zh0 = th * 8;
    const int zw0 = tw * 8;

    // acc[j]: co pair {2j, 2j+1}
    unsigned long long acc[16];
#pragma unroll
    for (int j = 0; j < 16; ++j) acc[j] = 0ull;

    const float* xn = x + (size_t)n * (CI * IN_S * IN_S * IN_S);

#pragma unroll 1
    for (int cc = 0; cc < NCHUNK; ++cc) {
        __syncthreads();
        // ---- load x halo tile: 8000 floats, zero-padded ----
        for (int i = tid; i < CIC * 1000; i += 512) {
            int ci = i / 1000;
            int r  = i - ci * 1000;
            int dd = r / 100;
            int r2 = r - dd * 100;
            int hh = r2 / 10;
            int ww = r2 - hh * 10;
            int gd = zd0 - 1 + dd;
            int gh = zh0 - 1 + hh;
            int gw = zw0 - 1 + ww;
            float v = 0.0f;
            if (gd >= 0 && gd < IN_S && gh >= 0 && gh < IN_S &&
                gw >= 0 && gw < IN_S)
                v = xn[(((cc * CIC + ci) * IN_S + gd) * IN_S + gh) * IN_S + gw];
            xs[ci][dd][hh][ww] = v;
        }
        // ---- load flipped weights: 6912 floats ----
        for (int i = tid; i < CIC * 27 * CO; i += 512) {
            int ci = i / (27 * CO);
            int r  = i - ci * (27 * CO);
            int k  = r >> 5;
            int co = r & 31;
            (&ws[0][0][0])[i] =
                w[((cc * CIC + ci) * CO + co) * 27 + (26 - k)];
        }
        __syncthreads();

        // ---- compute ----
#pragma unroll 1
        for (int ci = 0; ci < CIC; ++ci) {
            const float* xb = &xs[ci][ld][lh][lw];
#pragma unroll
            for (int kd = 0; kd < 3; ++kd)
#pragma unroll
            for (int kh = 0; kh < 3; ++kh)
#pragma unroll
            for (int kw = 0; kw < 3; ++kw) {
                float xv = xb[kd * 100 + kh * 10 + kw];
                unsigned long long xv2;
                asm("mov.b64 %0, {%1, %1};" : "=l"(xv2) : "f"(xv));
                const ulonglong2* wr =
                    reinterpret_cast<const ulonglong2*>(
                        &ws[ci][kd * 9 + kh * 3 + kw][0]);
#pragma unroll
                for (int j = 0; j < 8; ++j) {
                    ulonglong2 wv = wr[j];   // LDS.128, uniform -> broadcast
                    asm("fma.rn.f32x2 %0, %1, %2, %0;"
                        : "+l"(acc[2 * j])     : "l"(xv2), "l"(wv.x));
                    asm("fma.rn.f32x2 %0, %1, %2, %0;"
                        : "+l"(acc[2 * j + 1]) : "l"(xv2), "l"(wv.y));
                }
            }
        }
    }

    // ---- scatter to odd output positions + bias ----
    const int zd = zd0 + ld, zh = zh0 + lh, zw = zw0 + lw;
    const int od = 2 * zd + 1, oh = 2 * zh + 1, ow = 2 * zw + 1;
    float* outp = out + ((size_t)(n * CO) * OUT_S + od) * (OUT_S * OUT_S)
                      + oh * OUT_S + ow;
#pragma unroll
    for (int j = 0; j < 16; ++j) {
        float2 v;
        asm("mov.b64 {%0, %1}, %2;" : "=f"(v.x), "=f"(v.y) : "l"(acc[j]));
        float b0 = __ldg(&bias[2 * j]);
        float b1 = __ldg(&bias[2 * j + 1]);
        outp[(size_t)(2 * j) * CH_STRIDE]     = v.x + b0;
        outp[(size_t)(2 * j + 1) * CH_STRIDE] = v.y + b1;
    }
}

// ---------------------------------------------------------------------------
extern "C" void kernel_launch(void* const* d_in, const int* in_sizes, int n_in,
                              void* d_out, int out_size) {
    const float* x = nullptr;
    const float* w = nullptr;
    const float* b = nullptr;
    for (int i = 0; i < n_in; ++i) {
        if (in_sizes[i] == 4194304)    x = (const float*)d_in[i];
        else if (in_sizes[i] == 55296) w = (const float*)d_in[i];
        else if (in_sizes[i] == 32)    b = (const float*)d_in[i];
    }
    float* out = (float*)d_out;

    int fill_blocks = (OUT_F4 + 255) / 256;
    bias_fill_kernel<<<fill_blocks, 256>>>(b, out);

    dim3 grid(4, 4, 8);   // 128 blocks = one CTA per SM, single wave
    conv_core_kernel<<<grid, 512>>>(x, w, b, out);
}

// round 5
// speedup vs baseline: 1.3555x; 1.3555x over previous
#include <cuda_runtime.h>
#include <cstdint>

// x:      (2, 64, 32, 32, 32) fp32
// weight: (64, 32, 3, 3, 3)   fp32  (C_in, C_out, kD,kH,kW)
// bias:   (32,)               fp32
// out:    (2, 32, 66, 66, 66) fp32
//
// Only outputs with all-odd coords <= 63 carry conv data:
//   core[z] = sum_{ci,k} W[ci,co,2-kd,2-kh,2-kw] * x[ci, z-1+k]
// Everything else is bias-only.

#define N_BATCH 2
#define CI 64
#define CO 32
#define IN_S 32
#define OUT_S 66
#define CIC 8          // ci per smem chunk
#define NCHUNK (CI / CIC)
#define CH_STRIDE 287496   // 66^3
#define OUT_TOTAL 18399744 // 2*32*66^3
#define OUT_F4 (OUT_TOTAL / 4)
#define CH_F4 (CH_STRIDE / 4)

// ---------------------------------------------------------------------------
// Kernel 1: bias fill (vectorized float4). CH_STRIDE % 4 == 0 so each float4
// lies within one (n,co) channel.
// ---------------------------------------------------------------------------
__global__ void bias_fill_kernel(const float* __restrict__ bias,
                                 float* __restrict__ out) {
    int idx4 = blockIdx.x * blockDim.x + threadIdx.x;
    if (idx4 >= OUT_F4) return;
    int ch = idx4 / CH_F4;
    float b = __ldg(&bias[ch & 31]);
    reinterpret_cast<float4*>(out)[idx4] = make_float4(b, b, b, b);
}

// ---------------------------------------------------------------------------
// Kernel 2: dense 32^3 core conv.
// Block = 512 threads, (8,8,8) z-tile, CO split across thread halves:
//   tid < 256  -> co 0..15,   tid >= 256 -> co 16..31
//   within half: lw = tid&7, lh = (tid>>3)&7, ld = (tid>>6)&3
//   thread owns points (zd0+ld, zh, zw) and (zd0+ld+4, zh, zw) for its 16 co.
// Grid = (4,4,8) = 128 blocks -> one CTA per SM, single wave, 16 warps/SM.
// Per (ci,tap) per thread: 4 LDS.128 (w, broadcast) + 2 LDS.32 (x) + 2 mov
// + 16 fma.rn.f32x2  -> FMA-pipe bound.
// ---------------------------------------------------------------------------
__global__ void __launch_bounds__(512, 1)
conv_core_kernel(const float* __restrict__ x,
                 const float* __restrict__ w,
                 const float* __restrict__ bias,
                 float* __restrict__ out) {
    // x halo tile: [ci][10][10][10], zero-padded outside [0,32)
    __shared__ __align__(16) float xs[CIC][10][10][10];   // 32 KB
    // flipped weights: ws[ci][k][co], value = W[ci,co, 26-k]
    __shared__ __align__(16) float ws[CIC][27][CO];       // 27.6 KB

    const int tid = threadIdx.x;
    const int lw  = tid & 7;
    const int lh  = (tid >> 3) & 7;
    const int ld  = (tid >> 6) & 3;   // 0..3
    const int coh = tid >> 8;         // 0 or 1 -> co base 16*coh

    const int tw = blockIdx.x;        // 0..3
    const int th = blockIdx.y;        // 0..3
    const int nz = blockIdx.z;        // 0..7
    const int n  = nz >> 2;
    const int td = nz & 3;

    const int zd0 = td * 8;
    const int zh0 = th * 8;
    const int zw0 = tw * 8;

    // acc[p][j]: point p (zd0+ld+4p), co pair {coh*16+2j, coh*16+2j+1}
    unsigned long long acc[2][8];
#pragma unroll
    for (int p = 0; p < 2; ++p)
#pragma unroll
        for (int j = 0; j < 8; ++j) acc[p][j] = 0ull;

    const float* xn = x + (size_t)n * (CI * IN_S * IN_S * IN_S);

#pragma unroll 1
    for (int cc = 0; cc < NCHUNK; ++cc) {
        __syncthreads();
        // ---- load x halo tile: 8000 floats, zero-padded ----
        for (int i = tid; i < CIC * 1000; i += 512) {
            int ci = i / 1000;
            int r  = i - ci * 1000;
            int dd = r / 100;
            int r2 = r - dd * 100;
            int hh = r2 / 10;
            int ww = r2 - hh * 10;
            int gd = zd0 - 1 + dd;
            int gh = zh0 - 1 + hh;
            int gw = zw0 - 1 + ww;
            float v = 0.0f;
            if (gd >= 0 && gd < IN_S && gh >= 0 && gh < IN_S &&
                gw >= 0 && gw < IN_S)
                v = xn[(((cc * CIC + ci) * IN_S + gd) * IN_S + gh) * IN_S + gw];
            xs[ci][dd][hh][ww] = v;
        }
        // ---- load flipped weights: 6912 floats ----
        for (int i = tid; i < CIC * 27 * CO; i += 512) {
            int ci = i / (27 * CO);
            int r  = i - ci * (27 * CO);
            int k  = r >> 5;
            int co = r & 31;
            (&ws[0][0][0])[i] =
                w[((cc * CIC + ci) * CO + co) * 27 + (26 - k)];
        }
        __syncthreads();

        // ---- compute ----
#pragma unroll 1
        for (int ci = 0; ci < CIC; ++ci) {
            const float* xb0 = &xs[ci][ld][lh][lw];
            const float* xb1 = xb0 + 400;        // ld+4 plane
#pragma unroll
            for (int kd = 0; kd < 3; ++kd)
#pragma unroll
            for (int kh = 0; kh < 3; ++kh)
#pragma unroll
            for (int kw = 0; kw < 3; ++kw) {
                const int off = kd * 100 + kh * 10 + kw;
                float xv0 = xb0[off];
                float xv1 = xb1[off];
                unsigned long long xv20, xv21;
                asm("mov.b64 %0, {%1, %1};" : "=l"(xv20) : "f"(xv0));
                asm("mov.b64 %0, {%1, %1};" : "=l"(xv21) : "f"(xv1));
                const ulonglong2* wr =
                    reinterpret_cast<const ulonglong2*>(
                        &ws[ci][kd * 9 + kh * 3 + kw][coh * 16]);
#pragma unroll
                for (int q = 0; q < 4; ++q) {
                    ulonglong2 wv = wr[q];   // LDS.128, uniform -> broadcast
                    // wr[q] = co {base+4q .. base+4q+3} = pairs {2q, 2q+1}
                    asm("fma.rn.f32x2 %0, %1, %2, %0;"
                        : "+l"(acc[0][2 * q])     : "l"(xv20), "l"(wv.x));
                    asm("fma.rn.f32x2 %0, %1, %2, %0;"
                        : "+l"(acc[0][2 * q + 1]) : "l"(xv20), "l"(wv.y));
                    asm("fma.rn.f32x2 %0, %1, %2, %0;"
                        : "+l"(acc[1][2 * q])     : "l"(xv21), "l"(wv.x));
                    asm("fma.rn.f32x2 %0, %1, %2, %0;"
                        : "+l"(acc[1][2 * q + 1]) : "l"(xv21), "l"(wv.y));
                }
            }
        }
    }

    // ---- scatter to odd output positions + bias ----
    const int zh = zh0 + lh, zw = zw0 + lw;
    const int oh = 2 * zh + 1, ow = 2 * zw + 1;
#pragma unroll
    for (int p = 0; p < 2; ++p) {
        const int od = 2 * (zd0 + ld + 4 * p) + 1;
        float* outp = out
            + ((size_t)(n * CO + coh * 16) * OUT_S + od) * (OUT_S * OUT_S)
            + oh * OUT_S + ow;
#pragma unroll
        for (int j = 0; j < 8; ++j) {
            float2 v;
            asm("mov.b64 {%0, %1}, %2;" : "=f"(v.x), "=f"(v.y)
                                        : "l"(acc[p][j]));
            float b0 = __ldg(&bias[coh * 16 + 2 * j]);
            float b1 = __ldg(&bias[coh * 16 + 2 * j + 1]);
            outp[(size_t)(2 * j) * CH_STRIDE]     = v.x + b0;
            outp[(size_t)(2 * j + 1) * CH_STRIDE] = v.y + b1;
        }
    }
}

// ---------------------------------------------------------------------------
extern "C" void kernel_launch(void* const* d_in, const int* in_sizes, int n_in,
                              void* d_out, int out_size) {
    const float* x = nullptr;
    const float* w = nullptr;
    const float* b = nullptr;
    for (int i = 0; i < n_in; ++i) {
        if (in_sizes[i] == 4194304)    x = (const float*)d_in[i];
        else if (in_sizes[i] == 55296) w = (const float*)d_in[i];
        else if (in_sizes[i] == 32)    b = (const float*)d_in[i];
    }
    float* out = (float*)d_out;

    int fill_blocks = (OUT_F4 + 255) / 256;
    bias_fill_kernel<<<fill_blocks, 256>>>(b, out);

    dim3 grid(4, 4, 8);   // 128 blocks = one CTA per SM, single wave
    conv_core_kernel<<<grid, 512>>>(x, w, b, out);
}